// round 1
// baseline (speedup 1.0000x reference)
#include <cuda_runtime.h>
#include <math.h>

// Problem constants
#define NE   128          // n_e (inner GEMM dim)
#define NC   256          // rank*rank (output cols)
#define TILE_M 64         // matrices per block tile
#define BLK  256          // threads per block

// Shared: W (128*256 floats = 128KB) + A/C staging (64*128 floats = 32KB)
#define SMEM_FLOATS (NE*NC + TILE_M*NE)
#define SMEM_BYTES  (SMEM_FLOATS * 4)

__global__ __launch_bounds__(BLK, 1)
void jastrow_kernel(const float* __restrict__ occ,
                    const float* __restrict__ W,
                    const float* __restrict__ bias,
                    float* __restrict__ out,
                    int B)
{
    extern __shared__ float sm[];
    float* Wsh = sm;                 // [e][c], 128 x 256
    float* Ash = sm + NE * NC;       // [r][e], 64 x 128 ; reused as C staging (32 x 256)

    const int tid = threadIdx.x;
    const int tx  = tid & 31;        // 0..31 : column group
    const int ty  = tid >> 5;        // 0..7  : row group (== warp id)

    // ---- load W into shared once (coalesced, float4) ----
    {
        const float4* Wg = (const float4*)W;
        float4* Ws4 = (float4*)Wsh;
        for (int i = tid; i < NE * NC / 4; i += BLK) Ws4[i] = Wg[i];
    }

    // ---- bias for my 8 columns (cols: tx*4..tx*4+3 and 128+tx*4..+3) ----
    float breg[8];
    #pragma unroll
    for (int j = 0; j < 8; j++) {
        int c = (j < 4) ? (tx * 4 + j) : (128 + tx * 4 + (j - 4));
        breg[j] = bias[c];
    }

    const int ntiles = B / TILE_M;

    for (int tile = blockIdx.x; tile < ntiles; tile += gridDim.x) {
        const int m0 = tile * TILE_M;

        __syncthreads();   // previous epilogue fully done before overwriting Ash

        // ---- load A tile: Ash[r*128 + e] = occ[(m0+r)*128 + e] (direct copy, coalesced) ----
        {
            const float4* g4 = (const float4*)(occ + (size_t)m0 * NE);
            float4* As4 = (float4*)Ash;
            for (int i = tid; i < TILE_M * NE / 4; i += BLK) As4[i] = g4[i];
        }
        __syncthreads();

        // ---- GEMM: 8x8 register tile per thread ----
        float acc[8][8];
        #pragma unroll
        for (int i = 0; i < 8; i++)
            #pragma unroll
            for (int j = 0; j < 8; j++)
                acc[i][j] = 0.f;

        #pragma unroll 4
        for (int e = 0; e < NE; e++) {
            float a[8];
            #pragma unroll
            for (int i = 0; i < 8; i++)
                a[i] = Ash[(ty * 8 + i) * NE + e];   // warp-uniform (broadcast)
            float4 b0 = *(const float4*)&Wsh[e * NC + tx * 4];        // lanes consecutive: conflict-free
            float4 b1 = *(const float4*)&Wsh[e * NC + 128 + tx * 4];
            float b[8] = {b0.x, b0.y, b0.z, b0.w, b1.x, b1.y, b1.z, b1.w};
            #pragma unroll
            for (int i = 0; i < 8; i++)
                #pragma unroll
                for (int j = 0; j < 8; j++)
                    acc[i][j] = fmaf(a[i], b[j], acc[i][j]);
        }

        // ---- epilogue: two halves of 32 matrices through Ash staging ----
        for (int half = 0; half < 2; half++) {
            __syncthreads();
            // warps ty 0..3 own rows 0..31; ty 4..7 own rows 32..63
            if ((ty >> 2) == half) {
                #pragma unroll
                for (int i = 0; i < 8; i++) {
                    int rloc = (ty & 3) * 8 + i;     // 0..31 within this half
                    #pragma unroll
                    for (int j = 0; j < 8; j++) {
                        int c  = (j < 4) ? (tx * 4 + j) : (128 + tx * 4 + (j - 4));
                        int rr = c >> 4;             // row of 16x16 j-matrix
                        int cc = c & 15;             // col of 16x16 j-matrix
                        // lane cc of the LU half-warp wants its 16 values contiguous:
                        // store element (rr,cc) at [mat][cc*16 + rr]
                        Ash[rloc * 256 + cc * 16 + rr] = acc[i][j] + breg[j];
                    }
                }
            }
            __syncthreads();

            // ---- LU with partial pivoting: 16 half-warps, 2 matrices each ----
            const int hw = tid >> 4;   // 0..15
            const int l  = tid & 15;   // lane within half-warp

            for (int mm = 0; mm < 2; mm++) {
                const int mloc = hw * 2 + mm;        // 0..31
                // lane l holds row l of A = (I + j)^T  (same det)
                float a[16];
                #pragma unroll
                for (int k = 0; k < 16; k++)
                    a[k] = Ash[mloc * 256 + l * 16 + k] + (k == l ? 1.f : 0.f);

                bool  done   = false;
                float mylog  = 0.f;
                int   mysign = 1;
                int   pick   = 0;

                #pragma unroll
                for (int k = 0; k < 16; k++) {
                    // candidate pivot magnitude (done lanes excluded)
                    float v   = done ? -1.f : fabsf(a[k]);
                    int   idx = l;
                    // argmax over 16 lanes; tie-break to min lane index (must be deterministic!)
                    #pragma unroll
                    for (int off = 8; off; off >>= 1) {
                        float ov = __shfl_xor_sync(0xffffffffu, v,   off, 16);
                        int   oi = __shfl_xor_sync(0xffffffffu, idx, off, 16);
                        if (ov > v || (ov == v && oi < idx)) { v = ov; idx = oi; }
                    }
                    const int   p    = idx;
                    const float piv  = __shfl_sync(0xffffffffu, a[k], p, 16);
                    const bool  im_p = (l == p);
                    const float mult = (!done && !im_p) ? (a[k] / piv) : 0.f;
                    #pragma unroll
                    for (int jj = k + 1; jj < 16; jj++) {
                        float pr = __shfl_sync(0xffffffffu, a[jj], p, 16);
                        a[jj] -= mult * pr;
                    }
                    if (im_p) {
                        done = true;
                        pick = k;
                        mylog += logf(fabsf(piv));
                        if (piv < 0.f) mysign = -mysign;
                    }
                }

                // permutation parity: inversions of (lane -> pick step)
                int inv = 0;
                #pragma unroll
                for (int t = 0; t < 16; t++) {
                    int pt = __shfl_sync(0xffffffffu, pick, t, 16);
                    inv += (t < l && pt > pick) ? 1 : 0;
                }

                // reductions across the 16 lanes
                float logsum = mylog;
                int   invsum = inv;
                int   sgn    = mysign;
                #pragma unroll
                for (int off = 8; off; off >>= 1) {
                    logsum += __shfl_xor_sync(0xffffffffu, logsum, off, 16);
                    invsum += __shfl_xor_sync(0xffffffffu, invsum, off, 16);
                    sgn    *= __shfl_xor_sync(0xffffffffu, sgn,    off, 16);
                }

                if (l == 0) {
                    const int g = m0 + half * 32 + mloc;
                    float s = (float)sgn * ((invsum & 1) ? -1.f : 1.f);
                    out[g]     = s;        // j_sign
                    out[B + g] = logsum;   // j_logabs
                }
            }
        }
    }
}

extern "C" void kernel_launch(void* const* d_in, const int* in_sizes, int n_in,
                              void* d_out, int out_size)
{
    const float* occ  = (const float*)d_in[0];   // (B, 128) fp32
    const float* W    = (const float*)d_in[1];   // (128, 256) fp32
    const float* bias = (const float*)d_in[2];   // (256,) fp32
    float* out        = (float*)d_out;           // [sign(B); logabs(B)]
    const int B = in_sizes[0] / NE;

    cudaFuncSetAttribute(jastrow_kernel,
                         cudaFuncAttributeMaxDynamicSharedMemorySize, SMEM_BYTES);
    jastrow_kernel<<<148, BLK, SMEM_BYTES>>>(occ, W, bias, out, B);
}

// round 4
// speedup vs baseline: 1.1414x; 1.1414x over previous
#include <cuda_runtime.h>
#include <math.h>
#include <stdint.h>

#define NE     128
#define NC     256
#define TILE_M 128
#define BLK    512

// padded strides in 32-bit words (row length 128 + 4 pad -> conflict-free frag loads)
#define WSTR   132
#define ASTR   132

// smem byte offsets
#define SM_W     0              // 256*132*4 = 135168  : W fp32, [c][k]
#define SM_A     135168         // 128*132*4 = 67584   : A fp32, [m][k]
#define SM_CST   135168         // overlays A (A dead during epilogue): 32*273*4 = 34944
#define CST_MAT  273
#define SM_BIAS  202752         // 1024
#define SMEM_BYTES 203776

__device__ __forceinline__ uint32_t f2tf(float x) {
    uint32_t r;
    asm("cvt.rna.tf32.f32 %0, %1;" : "=r"(r) : "f"(x));
    return r;
}

#define MMA_TF32(c, a0, a1, a2, a3, b0, b1) \
    asm volatile("mma.sync.aligned.m16n8k8.row.col.f32.tf32.tf32.f32 " \
        "{%0,%1,%2,%3}, {%4,%5,%6,%7}, {%8,%9}, {%0,%1,%2,%3};" \
        : "+f"((c)[0]), "+f"((c)[1]), "+f"((c)[2]), "+f"((c)[3]) \
        : "r"(a0), "r"(a1), "r"(a2), "r"(a3), "r"(b0), "r"(b1))

__global__ __launch_bounds__(BLK, 1)
void jastrow_tf32_kernel(const float* __restrict__ occ,
                         const float* __restrict__ W,
                         const float* __restrict__ bias,
                         float* __restrict__ out,
                         int B)
{
    extern __shared__ char sm[];
    float* Wsh = (float*)(sm + SM_W);
    float* Ash = (float*)(sm + SM_A);
    float* cst = (float*)(sm + SM_CST);
    float* bs  = (float*)(sm + SM_BIAS);

    const int tid  = threadIdx.x;
    const int wid  = tid >> 5;
    const int lane = tid & 31;
    const int lq   = lane >> 2;      // 0..7
    const int lr   = lane & 3;       // 0..3
    const int mw   = wid >> 1;       // 0..7 : 16-row strip
    const int nw   = wid & 1;        // 0..1 : 128-col half
    const int hw   = tid >> 4;       // half-warp 0..31 (LU)
    const int l    = tid & 15;       // lane in half-warp (LU)

    // ---- load W once: Wsh[c][k] = W[k*256 + c] (coalesced in c) ----
    for (int i = tid; i < NE * NC; i += BLK) {
        int k = i >> 8;
        int c = i & 255;
        Wsh[c * WSTR + k] = W[k * NC + c];
    }
    for (int i = tid; i < NC; i += BLK) bs[i] = bias[i];
    __syncthreads();

    const int ntiles = B / TILE_M;

    for (int tile = blockIdx.x; tile < ntiles; tile += gridDim.x) {
        const int m0 = tile * TILE_M;

        // ---- A fill: straight fp32 copy with padded stride ----
        for (int i = tid; i < TILE_M * NE / 4; i += BLK) {
            int m = i >> 5;
            int k = (i & 31) * 4;
            float4 v = *(const float4*)(occ + (size_t)(m0 + m) * NE + k);
            *(float4*)(Ash + m * ASTR + k) = v;
        }
        __syncthreads();

        // ---- GEMM: warp (mw,nw) -> rows mw*16..+15, cols nw*128..+127 ----
        float acc[16][4];
        #pragma unroll
        for (int t = 0; t < 16; t++)
            #pragma unroll
            for (int e = 0; e < 4; e++) acc[t][e] = 0.f;

        const int ra = (mw * 16 + lq) * ASTR + lr;

        #pragma unroll 1
        for (int ks = 0; ks < 16; ks++) {
            // A fragment (m16 x k8) + tf32 hi/lo split
            float af[4];
            af[0] = Ash[ra + ks * 8];
            af[1] = Ash[ra + 8 * ASTR + ks * 8];
            af[2] = Ash[ra + ks * 8 + 4];
            af[3] = Ash[ra + 8 * ASTR + ks * 8 + 4];
            uint32_t ah[4], al[4];
            #pragma unroll
            for (int i = 0; i < 4; i++) {
                ah[i] = f2tf(af[i]);
                al[i] = f2tf(af[i] - __uint_as_float(ah[i]));
            }

            #pragma unroll
            for (int t = 0; t < 16; t++) {
                const int nb = (nw * 128 + t * 8 + lq) * WSTR + ks * 8 + lr;
                float b0 = Wsh[nb];
                float b1 = Wsh[nb + 4];
                uint32_t bh0 = f2tf(b0);
                uint32_t bl0 = f2tf(b0 - __uint_as_float(bh0));
                uint32_t bh1 = f2tf(b1);
                uint32_t bl1 = f2tf(b1 - __uint_as_float(bh1));
                MMA_TF32(acc[t], ah[0], ah[1], ah[2], ah[3], bh0, bh1);  // hi*hi
                MMA_TF32(acc[t], ah[0], ah[1], ah[2], ah[3], bl0, bl1);  // hi*lo
                MMA_TF32(acc[t], al[0], al[1], al[2], al[3], bh0, bh1);  // lo*hi
                MMA_TF32(acc[t], al[0], al[1], al[2], al[3], bl0, bl1);  // lo*lo
            }
        }
        __syncthreads();   // all GEMM smem reads done before staging overwrites A

        // ---- epilogue: 4 rounds of 32 matrices ----
        for (int s = 0; s < 4; s++) {
            if ((wid >> 2) == s) {
                const int rb = ((mw & 1) << 4) + lq;   // local row 0..31 in this round
                #pragma unroll
                for (int t = 0; t < 16; t++) {
                    const int cb = nw * 128 + t * 8 + 2 * lr;
                    #pragma unroll
                    for (int e = 0; e < 4; e++) {
                        int c = cb + (e & 1);
                        int r = rb + ((e >> 1) << 3);
                        // j element (rr=c>>4, cc=c&15) -> [mat][rr*17 + cc]
                        cst[r * CST_MAT + (c >> 4) * 17 + (c & 15)] = acc[t][e] + bs[c];
                    }
                }
            }
            __syncthreads();

            // ---- LU with partial pivoting: half-warp hw owns matrix hw ----
            {
                float a[16];
                #pragma unroll
                for (int k = 0; k < 16; k++)
                    a[k] = cst[hw * CST_MAT + k * 17 + l] + (k == l ? 1.f : 0.f);

                bool  done   = false;
                float mylog  = 0.f;
                int   mysign = 1;
                int   pick   = 0;

                #pragma unroll
                for (int k = 0; k < 16; k++) {
                    float v   = done ? -1.f : fabsf(a[k]);
                    int   idx = l;
                    #pragma unroll
                    for (int off = 8; off; off >>= 1) {
                        float ov = __shfl_xor_sync(0xffffffffu, v,   off, 16);
                        int   oi = __shfl_xor_sync(0xffffffffu, idx, off, 16);
                        if (ov > v || (ov == v && oi < idx)) { v = ov; idx = oi; }
                    }
                    const int   p    = idx;
                    const float piv  = __shfl_sync(0xffffffffu, a[k], p, 16);
                    const bool  im_p = (l == p);
                    const float mult = (!done && !im_p) ? (a[k] / piv) : 0.f;
                    #pragma unroll
                    for (int jj = k + 1; jj < 16; jj++) {
                        float pr = __shfl_sync(0xffffffffu, a[jj], p, 16);
                        a[jj] -= mult * pr;
                    }
                    if (im_p) {
                        done = true;
                        pick = k;
                        mylog += logf(fabsf(piv));
                        if (piv < 0.f) mysign = -mysign;
                    }
                }

                int inv = 0;
                #pragma unroll
                for (int t = 0; t < 16; t++) {
                    int pt = __shfl_sync(0xffffffffu, pick, t, 16);
                    inv += (t < l && pt > pick) ? 1 : 0;
                }

                float logsum = mylog;
                int   invsum = inv;
                int   sgn    = mysign;
                #pragma unroll
                for (int off = 8; off; off >>= 1) {
                    logsum += __shfl_xor_sync(0xffffffffu, logsum, off, 16);
                    invsum += __shfl_xor_sync(0xffffffffu, invsum, off, 16);
                    sgn    *= __shfl_xor_sync(0xffffffffu, sgn,    off, 16);
                }

                if (l == 0) {
                    const int g = m0 + s * 32 + hw;
                    float sg = (float)sgn * ((invsum & 1) ? -1.f : 1.f);
                    out[g]     = sg;       // j_sign
                    out[B + g] = logsum;   // j_logabs
                }
            }
            __syncthreads();   // cst reused next round / A refilled next tile
        }
    }
}

extern "C" void kernel_launch(void* const* d_in, const int* in_sizes, int n_in,
                              void* d_out, int out_size)
{
    const float* occ  = (const float*)d_in[0];   // (B, 128) fp32
    const float* W    = (const float*)d_in[1];   // (128, 256) fp32
    const float* bias = (const float*)d_in[2];   // (256,) fp32
    float* out        = (float*)d_out;           // [sign(B); logabs(B)]
    const int B = in_sizes[0] / NE;

    cudaFuncSetAttribute(jastrow_tf32_kernel,
                         cudaFuncAttributeMaxDynamicSharedMemorySize, SMEM_BYTES);
    jastrow_tf32_kernel<<<148, BLK, SMEM_BYTES>>>(occ, W, bias, out, B);
}